// round 13
// baseline (speedup 1.0000x reference)
#include <cuda_runtime.h>
#include <cuda_bf16.h>
#include <cstdint>

#define MARGIN 1.0f
#define NBLK   296          // 148 SMs * 2 CTAs -> one wave
#define NTHR   256
#define NQ     5            // a, sz, sz2, S, S2
#define PIPE   5            // ring stages
#define STG_F  1024         // floats per stage (4KB pred + 4KB lab)

// Per-block partials, [quantity][block]. __device__ globals => no allocation.
__device__ float        g_part[NQ * NBLK];
__device__ unsigned int g_count = 0;

__device__ __forceinline__ uint32_t smem_u32(const void* p) {
    uint32_t a;
    asm("{ .reg .u64 t; cvta.to.shared.u64 t, %1; cvt.u32.u64 %0, t; }"
        : "=r"(a) : "l"(p));
    return a;
}

__device__ __forceinline__ void mbar_init(uint32_t mbar, uint32_t cnt) {
    asm volatile("mbarrier.init.shared.b64 [%0], %1;" :: "r"(mbar), "r"(cnt) : "memory");
}
__device__ __forceinline__ void mbar_expect_tx(uint32_t mbar, uint32_t bytes) {
    asm volatile("mbarrier.arrive.expect_tx.shared.b64 _, [%0], %1;"
                 :: "r"(mbar), "r"(bytes) : "memory");
}
__device__ __forceinline__ void mbar_arrive(uint32_t mbar) {
    asm volatile("mbarrier.arrive.shared.b64 _, [%0];" :: "r"(mbar) : "memory");
}
__device__ __forceinline__ void mbar_wait(uint32_t mbar, uint32_t parity) {
    asm volatile(
        "{\n\t"
        ".reg .pred P;\n\t"
        "WL_%=:\n\t"
        "mbarrier.try_wait.parity.acquire.cta.shared::cta.b64 P, [%0], %1, 0x989680;\n\t"
        "@P bra.uni WD_%=;\n\t"
        "bra.uni WL_%=;\n\t"
        "WD_%=:\n\t"
        "}" :: "r"(mbar), "r"(parity) : "memory");
}
// Relaxed wait: OK for producer (post-wait accesses are async-proxy only).
__device__ __forceinline__ void mbar_wait_relaxed(uint32_t mbar, uint32_t parity) {
    asm volatile(
        "{\n\t"
        ".reg .pred P;\n\t"
        "WL_%=:\n\t"
        "mbarrier.try_wait.parity.relaxed.cta.shared::cta.b64 P, [%0], %1, 0x989680;\n\t"
        "@P bra.uni WD_%=;\n\t"
        "bra.uni WL_%=;\n\t"
        "WD_%=:\n\t"
        "}" :: "r"(mbar), "r"(parity) : "memory");
}
__device__ __forceinline__ void bulk_ld(uint32_t dst, const void* src,
                                        uint32_t bytes, uint32_t mbar) {
    asm volatile(
        "cp.async.bulk.shared::cluster.global.mbarrier::complete_tx::bytes "
        "[%0], [%1], %2, [%3];"
        :: "r"(dst), "l"(src), "r"(bytes), "r"(mbar) : "memory");
}

__device__ __forceinline__ float warp_sum(float v) {
    #pragma unroll
    for (int o = 16; o > 0; o >>= 1) v += __shfl_xor_sync(0xFFFFFFFFu, v, o);
    return v;
}
__device__ __forceinline__ double warp_sum_d(double v) {
    #pragma unroll
    for (int o = 16; o > 0; o >>= 1) v += __shfl_xor_sync(0xFFFFFFFFu, v, o);
    return v;
}

// Per-element update: unmasked S, S2; masked a, sz, sz2 (positives only).
__device__ __forceinline__ void acc1(float pv, int lv,
                                     float& a, float& sz, float& sz2,
                                     float& S, float& S2)
{
    S  += pv;
    S2  = fmaf(pv, pv, S2);
    float m = (lv == 1) ? 1.f : 0.f;
    float z = m * (MARGIN - pv);
    a  += m;
    sz += z;
    sz2 = fmaf(z, z, sz2);
}

__global__ __launch_bounds__(NTHR, 2) void sqloss_tma(
    const float* __restrict__ pred, const int* __restrict__ lab, int n,
    float* __restrict__ out)
{
    __shared__ __align__(128) float s_pred[PIPE][STG_F];   // 20KB
    __shared__ __align__(128) int   s_lab [PIPE][STG_F];   // 20KB
    __shared__ __align__(8)  uint64_t s_full [PIPE];
    __shared__ __align__(8)  uint64_t s_empty[PIPE];

    const int tid  = threadIdx.x;
    const int lane = tid & 31;
    const int wid  = tid >> 5;

    uint32_t fullb [PIPE];
    uint32_t emptyb[PIPE];
    #pragma unroll
    for (int s = 0; s < PIPE; s++) {
        fullb [s] = smem_u32(&s_full [s]);
        emptyb[s] = smem_u32(&s_empty[s]);
    }

    if (tid == 0) {
        #pragma unroll
        for (int s = 0; s < PIPE; s++) {
            mbar_init(fullb [s], 1);      // completed by TMA tx count
            mbar_init(emptyb[s], NTHR);   // all consumers arrive
        }
    }
    __syncthreads();

    // ── contiguous stage range for this CTA ──
    const int nStage = n / STG_F;                 // full stages in the input
    const int base   = nStage / NBLK;
    const int rem    = nStage - base * NBLK;
    const int cnt    = base + (blockIdx.x < rem ? 1 : 0);
    const int st0    = blockIdx.x * base + min((int)blockIdx.x, rem);

    // ── producer prologue: fill the ring (fresh barriers, no wait needed) ──
    if (tid == 0) {
        const int pre = cnt < PIPE ? cnt : PIPE;
        for (int k = 0; k < pre; k++) {
            mbar_expect_tx(fullb[k], 2 * STG_F * 4);
            bulk_ld(smem_u32(&s_pred[k][0]), pred + (size_t)(st0 + k) * STG_F,
                    STG_F * 4, fullb[k]);
            bulk_ld(smem_u32(&s_lab[k][0]),  lab  + (size_t)(st0 + k) * STG_F,
                    STG_F * 4, fullb[k]);
        }
    }

    float a = 0.f, sz = 0.f, sz2 = 0.f, S = 0.f, S2 = 0.f;

    // ── pipelined consume loop ──
    int slot = 0, phase = 0;
    for (int i = 0; i < cnt; i++) {
        mbar_wait(fullb[slot], phase);

        float4 pv = reinterpret_cast<const float4*>(&s_pred[slot][0])[tid];
        int4   lv = reinterpret_cast<const int4*>  (&s_lab [slot][0])[tid];
        acc1(pv.x, lv.x, a, sz, sz2, S, S2);
        acc1(pv.y, lv.y, a, sz, sz2, S, S2);
        acc1(pv.z, lv.z, a, sz, sz2, S, S2);
        acc1(pv.w, lv.w, a, sz, sz2, S, S2);

        mbar_arrive(emptyb[slot]);

        if (tid == 0) {
            int j = i + PIPE;
            if (j < cnt) {
                // Reissue into this slot once all NTHR consumers are done with
                // it. Empty-phase for iteration i is exactly `phase`.
                mbar_wait_relaxed(emptyb[slot], phase);
                mbar_expect_tx(fullb[slot], 2 * STG_F * 4);
                bulk_ld(smem_u32(&s_pred[slot][0]),
                        pred + (size_t)(st0 + j) * STG_F, STG_F * 4, fullb[slot]);
                bulk_ld(smem_u32(&s_lab[slot][0]),
                        lab  + (size_t)(st0 + j) * STG_F, STG_F * 4, fullb[slot]);
            }
        }
        if (++slot == PIPE) { slot = 0; phase ^= 1; }
    }

    // scalar tail (n not multiple of STG_F) — global thread 0 only
    if (blockIdx.x == 0 && tid == 0) {
        for (int j = nStage * STG_F; j < n; j++)
            acc1(pred[j], lab[j], a, sz, sz2, S, S2);
    }

    // ── block reduction ──
    __shared__ float sm[NQ][NTHR / 32];
    float vals[NQ] = {a, sz, sz2, S, S2};

    #pragma unroll
    for (int j = 0; j < NQ; j++) {
        float v = warp_sum(vals[j]);
        if (lane == 0) sm[j][wid] = v;
    }
    __syncthreads();

    if (wid == 0) {
        #pragma unroll
        for (int j = 0; j < NQ; j++) {
            float v = (lane < NTHR / 32) ? sm[j][lane] : 0.f;
            v = warp_sum(v);
            if (lane == 0) g_part[j * NBLK + blockIdx.x] = v;
        }
    }

    // ── last-block-done finalize ──
    __shared__ bool amLast;
    __threadfence();
    if (tid == 0) {
        unsigned int t = atomicAdd(&g_count, 1u);
        amLast = (t == gridDim.x - 1);
    }
    __syncthreads();

    if (amLast) {
        __shared__ double smd[NQ][NTHR / 32];
        double acc[NQ];
        #pragma unroll
        for (int j = 0; j < NQ; j++) {
            double v = 0.0;
            for (int b = tid; b < NBLK; b += NTHR)
                v += (double)g_part[j * NBLK + b];
            v = warp_sum_d(v);
            if (lane == 0) smd[j][wid] = v;
        }
        __syncthreads();
        if (wid == 0) {
            #pragma unroll
            for (int j = 0; j < NQ; j++) {
                double v = (lane < NTHR / 32) ? smd[j][lane] : 0.0;
                acc[j] = warp_sum_d(v);
            }
            if (lane == 0) {
                double A   = acc[0];
                double SZ  = acc[1];
                double SZ2 = acc[2];
                double Sd  = acc[3];
                double S2d = acc[4];
                double NN  = (double)n - A;                // n_neg
                double SP  = Sd  - (A - SZ);               // sum_neg p
                double SP2 = S2d - (A - 2.0 * SZ + SZ2);   // sum_neg p^2
                out[0] = (float)(A * SP2 + 2.0 * SZ * SP + SZ2 * NN);
                g_count = 0;   // reset for next graph replay
            }
        }
    }
}

extern "C" void kernel_launch(void* const* d_in, const int* in_sizes, int n_in,
                              void* d_out, int out_size)
{
    const float* pred = (const float*)d_in[0];
    const int*   lab  = (const int*)d_in[1];
    float*       out  = (float*)d_out;
    const int n = in_sizes[0];

    sqloss_tma<<<NBLK, NTHR>>>(pred, lab, n, out);
}

// round 14
// speedup vs baseline: 1.4019x; 1.4019x over previous
#include <cuda_runtime.h>
#include <cuda_bf16.h>
#include <cstdint>

#define MARGIN 1.0f
#define NBLK   296          // 148 SMs * 2 CTAs -> one wave
#define NTHR   256
#define NWARP  (NTHR / 32)
#define NQ     5            // a, sz, sz2, S, S2
#define PIPE   3            // ring stages
#define STG_F  4096         // floats per stage (16KB pred + 16KB lab)
#define F4_PER_STG (STG_F / 4)      // 1024 float4
#define F4_PER_THR (F4_PER_STG / NTHR)  // 4

// Per-block partials, [quantity][block]. __device__ globals => no allocation.
__device__ float        g_part[NQ * NBLK];
__device__ unsigned int g_count = 0;

__device__ __forceinline__ uint32_t smem_u32(const void* p) {
    uint32_t a;
    asm("{ .reg .u64 t; cvta.to.shared.u64 t, %1; cvt.u32.u64 %0, t; }"
        : "=r"(a) : "l"(p));
    return a;
}
__device__ __forceinline__ void mbar_init(uint32_t mbar, uint32_t cnt) {
    asm volatile("mbarrier.init.shared.b64 [%0], %1;" :: "r"(mbar), "r"(cnt) : "memory");
}
__device__ __forceinline__ void mbar_expect_tx(uint32_t mbar, uint32_t bytes) {
    asm volatile("mbarrier.arrive.expect_tx.shared.b64 _, [%0], %1;"
                 :: "r"(mbar), "r"(bytes) : "memory");
}
__device__ __forceinline__ void mbar_arrive(uint32_t mbar) {
    asm volatile("mbarrier.arrive.shared.b64 _, [%0];" :: "r"(mbar) : "memory");
}
__device__ __forceinline__ void mbar_wait(uint32_t mbar, uint32_t parity) {
    asm volatile(
        "{\n\t"
        ".reg .pred P;\n\t"
        "WL_%=:\n\t"
        "mbarrier.try_wait.parity.acquire.cta.shared::cta.b64 P, [%0], %1, 0x989680;\n\t"
        "@P bra.uni WD_%=;\n\t"
        "bra.uni WL_%=;\n\t"
        "WD_%=:\n\t"
        "}" :: "r"(mbar), "r"(parity) : "memory");
}
__device__ __forceinline__ void mbar_wait_relaxed(uint32_t mbar, uint32_t parity) {
    asm volatile(
        "{\n\t"
        ".reg .pred P;\n\t"
        "WL_%=:\n\t"
        "mbarrier.try_wait.parity.relaxed.cta.shared::cta.b64 P, [%0], %1, 0x989680;\n\t"
        "@P bra.uni WD_%=;\n\t"
        "bra.uni WL_%=;\n\t"
        "WD_%=:\n\t"
        "}" :: "r"(mbar), "r"(parity) : "memory");
}
__device__ __forceinline__ void bulk_ld(uint32_t dst, const void* src,
                                        uint32_t bytes, uint32_t mbar) {
    asm volatile(
        "cp.async.bulk.shared::cluster.global.mbarrier::complete_tx::bytes "
        "[%0], [%1], %2, [%3];"
        :: "r"(dst), "l"(src), "r"(bytes), "r"(mbar) : "memory");
}

__device__ __forceinline__ float warp_sum(float v) {
    #pragma unroll
    for (int o = 16; o > 0; o >>= 1) v += __shfl_xor_sync(0xFFFFFFFFu, v, o);
    return v;
}
__device__ __forceinline__ double warp_sum_d(double v) {
    #pragma unroll
    for (int o = 16; o > 0; o >>= 1) v += __shfl_xor_sync(0xFFFFFFFFu, v, o);
    return v;
}

// Per-element update: unmasked S, S2; masked a, sz, sz2 (positives only).
__device__ __forceinline__ void acc1(float pv, int lv,
                                     float& a, float& sz, float& sz2,
                                     float& S, float& S2)
{
    S  += pv;
    S2  = fmaf(pv, pv, S2);
    float m = (lv == 1) ? 1.f : 0.f;
    float z = m * (MARGIN - pv);
    a  += m;
    sz += z;
    sz2 = fmaf(z, z, sz2);
}

__global__ __launch_bounds__(NTHR, 2) void sqloss_tma(
    const float* __restrict__ pred, const int* __restrict__ lab, int n,
    float* __restrict__ out)
{
    __shared__ __align__(128) float s_pred[PIPE][STG_F];   // 48KB
    __shared__ __align__(128) int   s_lab [PIPE][STG_F];   // 48KB
    __shared__ __align__(8)  uint64_t s_full [PIPE];
    __shared__ __align__(8)  uint64_t s_empty[PIPE];

    const int tid  = threadIdx.x;
    const int lane = tid & 31;
    const int wid  = tid >> 5;

    uint32_t fullb [PIPE];
    uint32_t emptyb[PIPE];
    #pragma unroll
    for (int s = 0; s < PIPE; s++) {
        fullb [s] = smem_u32(&s_full [s]);
        emptyb[s] = smem_u32(&s_empty[s]);
    }

    if (tid == 0) {
        #pragma unroll
        for (int s = 0; s < PIPE; s++) {
            mbar_init(fullb [s], 1);      // completed by TMA tx bytes
            mbar_init(emptyb[s], NWARP);  // one arrive per warp (lane 0)
        }
    }
    __syncthreads();

    // ── contiguous stage range for this CTA ──
    const int nStage = n / STG_F;
    const int base   = nStage / NBLK;
    const int rem    = nStage - base * NBLK;
    const int cnt    = base + (blockIdx.x < rem ? 1 : 0);
    const int st0    = blockIdx.x * base + min((int)blockIdx.x, rem);

    // ── producer prologue: fill the ring ──
    if (tid == 0) {
        const int pre = cnt < PIPE ? cnt : PIPE;
        for (int k = 0; k < pre; k++) {
            mbar_expect_tx(fullb[k], 2 * STG_F * 4);
            bulk_ld(smem_u32(&s_pred[k][0]), pred + (size_t)(st0 + k) * STG_F,
                    STG_F * 4, fullb[k]);
            bulk_ld(smem_u32(&s_lab[k][0]),  lab  + (size_t)(st0 + k) * STG_F,
                    STG_F * 4, fullb[k]);
        }
    }

    float a = 0.f, sz = 0.f, sz2 = 0.f, S = 0.f, S2 = 0.f;

    // ── pipelined consume loop ──
    int slot = 0, phase = 0;
    for (int i = 0; i < cnt; i++) {
        mbar_wait(fullb[slot], phase);

        const float4* sp = reinterpret_cast<const float4*>(&s_pred[slot][0]);
        const int4*   sl = reinterpret_cast<const int4*>  (&s_lab [slot][0]);
        #pragma unroll
        for (int k = 0; k < F4_PER_THR; k++) {
            float4 pv = sp[k * NTHR + tid];
            int4   lv = sl[k * NTHR + tid];
            acc1(pv.x, lv.x, a, sz, sz2, S, S2);
            acc1(pv.y, lv.y, a, sz, sz2, S, S2);
            acc1(pv.z, lv.z, a, sz, sz2, S, S2);
            acc1(pv.w, lv.w, a, sz, sz2, S, S2);
        }

        // one arrive per warp, after the whole warp's reads are done
        __syncwarp();
        if (lane == 0) mbar_arrive(emptyb[slot]);

        if (tid == 0) {
            int j = i + PIPE;
            if (j < cnt) {
                mbar_wait_relaxed(emptyb[slot], phase);   // all 8 warps done
                mbar_expect_tx(fullb[slot], 2 * STG_F * 4);
                bulk_ld(smem_u32(&s_pred[slot][0]),
                        pred + (size_t)(st0 + j) * STG_F, STG_F * 4, fullb[slot]);
                bulk_ld(smem_u32(&s_lab[slot][0]),
                        lab  + (size_t)(st0 + j) * STG_F, STG_F * 4, fullb[slot]);
            }
        }
        if (++slot == PIPE) { slot = 0; phase ^= 1; }
    }

    // scalar tail (n not multiple of STG_F) — global thread 0 only
    if (blockIdx.x == 0 && tid == 0) {
        for (int j = nStage * STG_F; j < n; j++)
            acc1(pred[j], lab[j], a, sz, sz2, S, S2);
    }

    // ── block reduction ──
    __shared__ float sm[NQ][NWARP];
    float vals[NQ] = {a, sz, sz2, S, S2};

    #pragma unroll
    for (int j = 0; j < NQ; j++) {
        float v = warp_sum(vals[j]);
        if (lane == 0) sm[j][wid] = v;
    }
    __syncthreads();

    if (wid == 0) {
        #pragma unroll
        for (int j = 0; j < NQ; j++) {
            float v = (lane < NWARP) ? sm[j][lane] : 0.f;
            v = warp_sum(v);
            if (lane == 0) g_part[j * NBLK + blockIdx.x] = v;
        }
    }

    // ── last-block-done finalize ──
    __shared__ bool amLast;
    __threadfence();
    if (tid == 0) {
        unsigned int t = atomicAdd(&g_count, 1u);
        amLast = (t == gridDim.x - 1);
    }
    __syncthreads();

    if (amLast) {
        __shared__ double smd[NQ][NWARP];
        double acc[NQ];
        #pragma unroll
        for (int j = 0; j < NQ; j++) {
            double v = 0.0;
            for (int b = tid; b < NBLK; b += NTHR)
                v += (double)g_part[j * NBLK + b];
            v = warp_sum_d(v);
            if (lane == 0) smd[j][wid] = v;
        }
        __syncthreads();
        if (wid == 0) {
            #pragma unroll
            for (int j = 0; j < NQ; j++) {
                double v = (lane < NWARP) ? smd[j][lane] : 0.0;
                acc[j] = warp_sum_d(v);
            }
            if (lane == 0) {
                double A   = acc[0];
                double SZ  = acc[1];
                double SZ2 = acc[2];
                double Sd  = acc[3];
                double S2d = acc[4];
                double NN  = (double)n - A;                // n_neg
                double SP  = Sd  - (A - SZ);               // sum_neg p
                double SP2 = S2d - (A - 2.0 * SZ + SZ2);   // sum_neg p^2
                out[0] = (float)(A * SP2 + 2.0 * SZ * SP + SZ2 * NN);
                g_count = 0;   // reset for next graph replay
            }
        }
    }
}

extern "C" void kernel_launch(void* const* d_in, const int* in_sizes, int n_in,
                              void* d_out, int out_size)
{
    const float* pred = (const float*)d_in[0];
    const int*   lab  = (const int*)d_in[1];
    float*       out  = (float*)d_out;
    const int n = in_sizes[0];

    sqloss_tma<<<NBLK, NTHR>>>(pred, lab, n, out);
}